// round 5
// baseline (speedup 1.0000x reference)
#include <cuda_runtime.h>
#include <math.h>
#include <stdint.h>

#define NB 4
#define NP 8
#define NN 512
#define DM 128
#define NH 4
#define DK 32
#define NT 3
#define NROWS (NB*NP*NN)     // 16384
#define MAXNNZ 128
#define LISTDIM 136          // padded list dim (>= MAXNNZ+1 for prefetch pad)
#define LDP 132              // smem row stride (floats) for GEMM tiles

// Scratch (device globals)
__device__ float g_qkv[9][NROWS][DM];    // [t*3 + {Q,K,V}][row][d]
__device__ float g_attn[NT][NROWS][DM];  // per-t attention output
__device__ int   g_cnt[NT][NN];
__device__ int   g_rank[NT][NN];         // row n -> rank (sorted by cnt asc)
__device__ int   g_rowOfRank[NT][NN];    // rank -> row n
__device__ int   g_nnzR[NT][NN];         // cnt indexed by rank
__device__ int   g_colsT[NT][LISTDIM][NN];   // [t][i][rank] -> coalesced over rank
__device__ float g_valsT[NT][LISTDIM][NN];

__constant__ int c_which[NT] = {0, 1, 3};

// ---------------------------------------------------------------------------
__device__ __forceinline__ uint32_t f2tf32(float f) {
    uint32_t r; asm("cvt.rna.tf32.f32 %0, %1;" : "=r"(r) : "f"(f)); return r;
}
// m16n8k8 tf32 MMA, D += A*B (row x col)
__device__ __forceinline__ void mma8(float d[4], const uint32_t a[4], const uint32_t b[2]) {
    asm volatile("mma.sync.aligned.m16n8k8.row.col.f32.tf32.tf32.f32 "
        "{%0,%1,%2,%3}, {%4,%5,%6,%7}, {%8,%9}, {%0,%1,%2,%3};"
        : "+f"(d[0]), "+f"(d[1]), "+f"(d[2]), "+f"(d[3])
        : "r"(a[0]), "r"(a[1]), "r"(a[2]), "r"(a[3]), "r"(b[0]), "r"(b[1]));
}

// ===========================================================================
// Kernel 1a: count nonzeros per selected-tm row
// ===========================================================================
__global__ void count_kernel(const float* __restrict__ tmall) {
    int wg   = (blockIdx.x * blockDim.x + threadIdx.x) >> 5;
    int lane = threadIdx.x & 31;
    if (wg >= NT * NN) return;
    int t = wg / NN, n = wg % NN;
    const float* row = tmall + ((size_t)c_which[t] * NN + n) * NN;
    int cnt = 0;
    for (int base = 0; base < NN; base += 32)
        cnt += __popc(__ballot_sync(0xffffffffu, row[base + lane] != 0.0f));
    if (lane == 0) g_cnt[t][n] = cnt < MAXNNZ ? cnt : MAXNNZ;
}

// ===========================================================================
// Kernel 1b: rank rows by cnt (stable, deterministic). Block per t.
// ===========================================================================
__global__ void rank_kernel() {
    __shared__ int sc[NN];
    int t = blockIdx.x, n = threadIdx.x;
    sc[n] = g_cnt[t][n];
    __syncthreads();
    int c = sc[n], r = 0;
    for (int m = 0; m < NN; m++) {
        int cm = sc[m];
        r += (cm < c) || (cm == c && m < n);
    }
    g_rank[t][n] = r;
    g_rowOfRank[t][r] = n;
    g_nnzR[t][r] = c;
}

// ===========================================================================
// Kernel 1c: fill transposed CSR at rank column (+1 zero pad for prefetch)
// ===========================================================================
__global__ void fill_kernel(const float* __restrict__ tmall) {
    int wg   = (blockIdx.x * blockDim.x + threadIdx.x) >> 5;
    int lane = threadIdx.x & 31;
    if (wg >= NT * NN) return;
    int t = wg / NN, n = wg % NN;
    int rk = g_rank[t][n];
    const float* row = tmall + ((size_t)c_which[t] * NN + n) * NN;
    int cnt = 0;
    for (int base = 0; base < NN; base += 32) {
        float v = row[base + lane];
        unsigned b = __ballot_sync(0xffffffffu, v != 0.0f);
        if (v != 0.0f) {
            int pos = cnt + __popc(b & ((1u << lane) - 1u));
            if (pos < MAXNNZ) { g_colsT[t][pos][rk] = base + lane; g_valsT[t][pos][rk] = v; }
        }
        cnt += __popc(b);
    }
    if (lane == 0) {
        int cc = cnt < MAXNNZ ? cnt : MAXNNZ;
        g_colsT[t][cc][rk] = 0;      // pad entry for prefetch
        g_valsT[t][cc][rk] = 0.0f;
    }
}

// ===========================================================================
// Kernel 2: QKV projections via tf32 mma.sync. 64-row tiles, 256 threads,
// 2 CTAs/SM. 8 warps as 2(m)x4(n); 9 weight slots, single W smem buffer
// (cross-CTA overlap hides staging).
// ===========================================================================
__global__ void __launch_bounds__(256, 2)
qkv_mma_kernel(const float* __restrict__ X,
               const float* __restrict__ Wq,
               const float* __restrict__ Wk,
               const float* __restrict__ Wv) {
    extern __shared__ uint32_t sm[];
    uint32_t* Xs = sm;                // [64][LDP]
    uint32_t* Ws = sm + 64 * LDP;     // [128][LDP]
    int tid = threadIdx.x, lane = tid & 31, wid = tid >> 5;
    int mw = wid & 1, nw = wid >> 1;
    int g = lane >> 2, q = lane & 3;
    int row0 = blockIdx.x * 64;

    for (int i = tid; i < 64 * 32; i += 256) {
        int r = i >> 5, k = (i & 31) << 2;
        float4 v = *(const float4*)(X + (size_t)(row0 + r) * DM + k);
        uint32_t* d = Xs + r * LDP + k;
        d[0] = f2tf32(v.x); d[1] = f2tf32(v.y); d[2] = f2tf32(v.z); d[3] = f2tf32(v.w);
    }
    const float* Wbase[3] = {Wq, Wk, Wv};
    const uint32_t* abase = Xs + (mw * 32 + g) * LDP + q;
    const uint32_t* bbase = Ws + (nw * 32 + g) * LDP + q;

    for (int slot = 0; slot < 9; slot++) {
        __syncthreads();   // prev MMA done (and X staged on iter 0)
        const float* W = Wbase[slot % 3] + (size_t)(slot / 3) * DM * DM;
        for (int i = tid; i < 128 * 32; i += 256) {
            int r = i >> 5, k = (i & 31) << 2;
            float4 v = *(const float4*)(W + (size_t)r * DM + k);
            uint32_t* d = Ws + r * LDP + k;
            d[0] = f2tf32(v.x); d[1] = f2tf32(v.y); d[2] = f2tf32(v.z); d[3] = f2tf32(v.w);
        }
        __syncthreads();

        float acc[2][4][4];
        #pragma unroll
        for (int t2 = 0; t2 < 2; t2++)
            #pragma unroll
            for (int j = 0; j < 4; j++)
                #pragma unroll
                for (int e = 0; e < 4; e++) acc[t2][j][e] = 0.f;

        #pragma unroll 4
        for (int ks = 0; ks < 16; ks++) {
            int k0 = ks * 8;
            uint32_t a[2][4];
            #pragma unroll
            for (int t2 = 0; t2 < 2; t2++) {
                const uint32_t* ap = abase + t2 * 16 * LDP + k0;
                a[t2][0] = ap[0]; a[t2][1] = ap[8 * LDP];
                a[t2][2] = ap[4]; a[t2][3] = ap[8 * LDP + 4];
            }
            #pragma unroll
            for (int j = 0; j < 4; j++) {
                const uint32_t* bp = bbase + j * 8 * LDP + k0;
                uint32_t b[2]; b[0] = bp[0]; b[1] = bp[4];
                mma8(acc[0][j], a[0], b);
                mma8(acc[1][j], a[1], b);
            }
        }
        float* out = &g_qkv[slot][row0][0];
        #pragma unroll
        for (int t2 = 0; t2 < 2; t2++) {
            int r = mw * 32 + t2 * 16 + g;
            #pragma unroll
            for (int j = 0; j < 4; j++) {
                int c = nw * 32 + j * 8 + q * 2;
                *(float2*)(out + (size_t)r * DM + c)       = make_float2(acc[t2][j][0], acc[t2][j][1]);
                *(float2*)(out + (size_t)(r + 8) * DM + c) = make_float2(acc[t2][j][2], acc[t2][j][3]);
            }
        }
    }
}

// ===========================================================================
// Kernel 3: sparse-masked attention. Block = (t,bp,h), 512 threads, thread =
// rank rk (rows sorted by nnz -> uniform warp iteration counts). K/V in SMEM
// stride-32, lane-rotated float4 reads (4-phase crossbar floor). Direct exp;
// coalesced transposed CSR; next-(m,tv) software prefetch.
// ===========================================================================
__global__ void __launch_bounds__(512, 1)
attn_kernel() {
    extern __shared__ float smf[];
    float* Ks = smf;               // [512][32]
    float* Vs = smf + 512 * 32;    // [512][32]
    int tid = threadIdx.x;
    int h = blockIdx.x;
    int t = blockIdx.y >> 5, bp = blockIdx.y & 31;

    const float* Kg = &g_qkv[t * 3 + 1][(size_t)bp * NN][0];
    const float* Vg = &g_qkv[t * 3 + 2][(size_t)bp * NN][0];
    for (int i = tid; i < 512 * 8; i += 512) {
        int m = i >> 3, j = i & 7;
        float4 kv = *(const float4*)(Kg + (size_t)m * DM + h * DK + j * 4);
        float4 vv = *(const float4*)(Vg + (size_t)m * DM + h * DK + j * 4);
        *(float4*)(Ks + m * 32 + j * 4) = kv;
        *(float4*)(Vs + m * 32 + j * 4) = vv;
    }
    __syncthreads();

    int rk = tid;
    int n = g_rowOfRank[t][rk];
    int gn = bp * NN + n;
    int rot = tid & 7;
    float4 qr[8];
    const float* Qg = &g_qkv[t * 3 + 0][gn][h * DK];
    #pragma unroll
    for (int j = 0; j < 8; j++) {
        int jj = (j + rot) & 7;
        qr[j] = *(const float4*)(Qg + jj * 4);
    }
    int cnt = g_nnzR[t][rk];
    float Z = 0.f;
    float4 av[8];
    #pragma unroll
    for (int j = 0; j < 8; j++) av[j] = make_float4(0.f, 0.f, 0.f, 0.f);
    const float scale = 0.17677669529663687f;   // 1/sqrt(32)

    int m = g_colsT[t][0][rk];
    float tv = g_valsT[t][0][rk];
    for (int i = 0; i < cnt; i++) {
        int m2 = g_colsT[t][i + 1][rk];       // pad entry makes this safe
        float tv2 = g_valsT[t][i + 1][rk];
        const float* kb = Ks + m * 32;
        float s = 0.f;
        #pragma unroll
        for (int j = 0; j < 8; j++) {
            int jj = (j + rot) & 7;
            float4 k4 = *(const float4*)(kb + jj * 4);
            s += qr[j].x * k4.x + qr[j].y * k4.y + qr[j].z * k4.z + qr[j].w * k4.w;
        }
        float e = __expf(s * scale);
        Z += e;
        float we = tv * e;
        const float* vb = Vs + m * 32;
        #pragma unroll
        for (int j = 0; j < 8; j++) {
            int jj = (j + rot) & 7;
            float4 v4 = *(const float4*)(vb + jj * 4);
            av[j].x += we * v4.x;
            av[j].y += we * v4.y;
            av[j].z += we * v4.z;
            av[j].w += we * v4.w;
        }
        m = m2; tv = tv2;
    }
    float inv = 1.f / Z;
    float* out = &g_attn[t][gn][h * DK];
    #pragma unroll
    for (int j = 0; j < 8; j++) {
        int jj = (j + rot) & 7;
        float4 v = make_float4(av[j].x * inv, av[j].y * inv, av[j].z * inv, av[j].w * inv);
        *(float4*)(out + jj * 4) = v;
    }
}

// ===========================================================================
// Kernel 4: output projection via tf32 mma.sync (K=384 = 3 accumulated
// chunks). 64-row tiles, 256 threads, 2 CTAs/SM; fused residual + LN.
// ===========================================================================
__global__ void __launch_bounds__(256, 2)
outproj_mma_kernel(const float* __restrict__ X,
                   const float* __restrict__ Wo,
                   const float* __restrict__ gamma,
                   const float* __restrict__ beta,
                   float* __restrict__ out) {
    extern __shared__ uint32_t sm[];
    uint32_t* As = sm;                // [64][LDP]
    uint32_t* Ws = sm + 64 * LDP;     // [128][LDP]
    float* Ys = (float*)sm;           // reuse As after GEMM
    int tid = threadIdx.x, lane = tid & 31, wid = tid >> 5;
    int mw = wid & 1, nw = wid >> 1;
    int g = lane >> 2, q = lane & 3;
    int row0 = blockIdx.x * 64;

    const uint32_t* abase = As + (mw * 32 + g) * LDP + q;
    const uint32_t* bbase = Ws + (nw * 32 + g) * LDP + q;

    float acc[2][4][4];
    #pragma unroll
    for (int t2 = 0; t2 < 2; t2++)
        #pragma unroll
        for (int j = 0; j < 4; j++)
            #pragma unroll
            for (int e = 0; e < 4; e++) acc[t2][j][e] = 0.f;

    for (int t = 0; t < NT; t++) {
        __syncthreads();
        for (int i = tid; i < 64 * 32; i += 256) {
            int r = i >> 5, k = (i & 31) << 2;
            float4 a = *(const float4*)(&g_attn[t][row0 + r][k]);
            uint32_t* d = As + r * LDP + k;
            d[0] = f2tf32(a.x); d[1] = f2tf32(a.y); d[2] = f2tf32(a.z); d[3] = f2tf32(a.w);
        }
        for (int i = tid; i < 128 * 32; i += 256) {
            int r = i >> 5, k = (i & 31) << 2;
            float4 w = *(const float4*)(Wo + (size_t)r * (NT * DM) + t * DM + k);
            uint32_t* d2 = Ws + r * LDP + k;
            d2[0] = f2tf32(w.x); d2[1] = f2tf32(w.y); d2[2] = f2tf32(w.z); d2[3] = f2tf32(w.w);
        }
        __syncthreads();
        #pragma unroll 4
        for (int ks = 0; ks < 16; ks++) {
            int k0 = ks * 8;
            uint32_t a[2][4];
            #pragma unroll
            for (int t2 = 0; t2 < 2; t2++) {
                const uint32_t* ap = abase + t2 * 16 * LDP + k0;
                a[t2][0] = ap[0]; a[t2][1] = ap[8 * LDP];
                a[t2][2] = ap[4]; a[t2][3] = ap[8 * LDP + 4];
            }
            #pragma unroll
            for (int j = 0; j < 4; j++) {
                const uint32_t* bp = bbase + j * 8 * LDP + k0;
                uint32_t b[2]; b[0] = bp[0]; b[1] = bp[4];
                mma8(acc[0][j], a[0], b);
                mma8(acc[1][j], a[1], b);
            }
        }
    }
    __syncthreads();
    #pragma unroll
    for (int t2 = 0; t2 < 2; t2++) {
        int r = mw * 32 + t2 * 16 + g;
        #pragma unroll
        for (int j = 0; j < 4; j++) {
            int c = nw * 32 + j * 8 + q * 2;
            *(float2*)(Ys + r * LDP + c)       = make_float2(acc[t2][j][0], acc[t2][j][1]);
            *(float2*)(Ys + (r + 8) * LDP + c) = make_float2(acc[t2][j][2], acc[t2][j][3]);
        }
    }
    __syncthreads();
    // warp-per-row residual + LayerNorm (8 warps x 8 rows)
    for (int r = wid; r < 64; r += 8) {
        float4 y  = *(float4*)(Ys + r * LDP + lane * 4);
        float4 xv = *(const float4*)(X + (size_t)(row0 + r) * DM + lane * 4);
        float v0 = y.x + xv.x, v1 = y.y + xv.y, v2 = y.z + xv.z, v3 = y.w + xv.w;
        float s  = v0 + v1 + v2 + v3;
        float s2 = v0 * v0 + v1 * v1 + v2 * v2 + v3 * v3;
        #pragma unroll
        for (int off = 16; off; off >>= 1) {
            s  += __shfl_xor_sync(0xffffffffu, s,  off);
            s2 += __shfl_xor_sync(0xffffffffu, s2, off);
        }
        float mu = s * (1.f / DM);
        float var = s2 * (1.f / DM) - mu * mu;
        float rs = rsqrtf(var + 1e-5f);
        float4 gv = *(const float4*)(gamma + lane * 4);
        float4 bv = *(const float4*)(beta + lane * 4);
        float4 res = make_float4((v0 - mu) * rs * gv.x + bv.x,
                                 (v1 - mu) * rs * gv.y + bv.y,
                                 (v2 - mu) * rs * gv.z + bv.z,
                                 (v3 - mu) * rs * gv.w + bv.w);
        *(float4*)(out + (size_t)(row0 + r) * DM + lane * 4) = res;
    }
}

// ===========================================================================
extern "C" void kernel_launch(void* const* d_in, const int* in_sizes, int n_in,
                              void* d_out, int out_size) {
    const float* inputs = (const float*)d_in[0];
    const float* tm     = (const float*)d_in[2];
    const float* Wq     = (const float*)d_in[3];
    const float* Wk     = (const float*)d_in[4];
    const float* Wv     = (const float*)d_in[5];
    const float* Wo     = (const float*)d_in[6];
    const float* gamma  = (const float*)d_in[7];
    const float* beta   = (const float*)d_in[8];
    float* out = (float*)d_out;

    int smem_gemm = (64 + 128) * LDP * (int)sizeof(float);   // 101376
    int smem_attn = 2 * 512 * 32 * (int)sizeof(float);       // 131072
    cudaFuncSetAttribute(qkv_mma_kernel,     cudaFuncAttributeMaxDynamicSharedMemorySize, smem_gemm);
    cudaFuncSetAttribute(attn_kernel,        cudaFuncAttributeMaxDynamicSharedMemorySize, smem_attn);
    cudaFuncSetAttribute(outproj_mma_kernel, cudaFuncAttributeMaxDynamicSharedMemorySize, smem_gemm);

    count_kernel<<<(NT * NN * 32 + 255) / 256, 256>>>(tm);
    rank_kernel<<<NT, NN>>>();
    fill_kernel<<<(NT * NN * 32 + 255) / 256, 256>>>(tm);
    qkv_mma_kernel<<<NROWS / 64, 256, smem_gemm>>>(inputs, Wq, Wk, Wv);
    attn_kernel<<<dim3(NH, NT * NB * NP), 512, smem_attn>>>();
    outproj_mma_kernel<<<NROWS / 64, 256, smem_gemm>>>(inputs, Wo, gamma, beta, out);
}